// round 16
// baseline (speedup 1.0000x reference)
#include <cuda_runtime.h>
#include <cuda_fp16.h>
typedef unsigned long long u64;

#define TT 2048
#define BB 4096
#define OUTLEN 25
#define TPW 20             // batches per warp: 10 pairs x 2 packed
#define WPD 205            // warps per direction
#define NWIN (TT/8)        // 256 windows of 8 steps

__device__ float g_y[BB * 18];

__device__ __forceinline__ u64 pack2(float lo, float hi) {
    u64 d; asm("mov.b64 %0,{%1,%2};" : "=l"(d) : "f"(lo), "f"(hi)); return d;
}
__device__ __forceinline__ void unpack2(u64 v, float& lo, float& hi) {
    asm("mov.b64 {%0,%1},%2;" : "=f"(lo), "=f"(hi) : "l"(v));
}
__device__ __forceinline__ u64 fma2(u64 a, u64 b, u64 c) {
    u64 d; asm("fma.rn.f32x2 %0,%1,%2,%3;" : "=l"(d) : "l"(a), "l"(b), "l"(c)); return d;
}
__device__ __forceinline__ u64 mul2(u64 a, u64 b) {
    u64 d; asm("mul.rn.f32x2 %0,%1,%2;" : "=l"(d) : "l"(a), "l"(b)); return d;
}
__device__ __forceinline__ u64 add2(u64 a, u64 b) {
    u64 d; asm("add.rn.f32x2 %0,%1,%2;" : "=l"(d) : "l"(a), "l"(b)); return d;
}
__device__ __forceinline__ __half2 tanh2(__half2 z) {
    unsigned zi = *reinterpret_cast<unsigned*>(&z);
    unsigned y; asm("tanh.approx.f16x2 %0,%1;" : "=r"(y) : "r"(zi));
    return *reinterpret_cast<__half2*>(&y);
}
__device__ __forceinline__ __half2 shfl_h2(__half2 v, int src) {
    unsigned u = *reinterpret_cast<unsigned*>(&v);
    u = __shfl_sync(0xffffffffu, u, src);
    return *reinterpret_cast<__half2*>(&u);
}
__device__ __forceinline__ float ftanh(float x) {
    x = fminf(fmaxf(x, -9.0f), 9.0f);
    float e = __expf(2.0f * x);
    return __fdividef(e - 1.0f, e + 1.0f);
}

__global__ void dummy_kernel() {}

// ---------------------------------------------------------------------------
// Stage 1: bidirectional Elman RNN H1=9 over T=2048.
// R13 structure (410 warps = 103 CTAs x 4, 1 warp/SMSP; cp.async f32 x
// staging; f16x2 main phase; f32x2 precise tail for the last 32 steps).
// CHANGE vs R13: the per-step 6-SHFL burst (MIO rt ~8 -> ~48 exposed cyc) is
// broken up: per m we do tanh(m) -> 2 shfl(m) -> next-step zx chunk(m), so
// each shfl pair has adjacent MUFU/fma work to overlap its MIO issue.
// ---------------------------------------------------------------------------
__global__ __launch_bounds__(128, 1) void rnn1_kernel(
    const float* __restrict__ x,
    const float* __restrict__ wih_f, const float* __restrict__ whh_f,
    const float* __restrict__ bih_f, const float* __restrict__ bhh_f,
    const float* __restrict__ wih_b, const float* __restrict__ whh_b,
    const float* __restrict__ bih_b, const float* __restrict__ bhh_b)
{
    __shared__ float4 sx4[4][2][210];

    const int wIn  = threadIdx.x >> 5;
    const int lane = threadIdx.x & 31;
    const int wid  = blockIdx.x * 4 + wIn;
    if (wid >= 2 * WPD) return;

    const bool bwd = (wid >= WPD);
    const int  wg  = bwd ? wid - WPD : wid;
    const int  tri = min(lane / 3, 9);     // lanes 30,31 shadow pair 9
    const int  r   = lane % 3;
    const int  rA  = (r + 1) % 3, rB = (r + 2) % 3;
    const int  laneA = 3 * tri + rA, laneB = 3 * tri + rB;

    const float* wih = bwd ? wih_b : wih_f;
    const float* whh = bwd ? whh_b : whh_f;
    const float* bih = bwd ? bih_b : bih_f;
    const float* bhh = bwd ? bhh_b : bhh_f;

    __half2 WX16[3][5], WhO16[3][3], WhA16[3][3], WhB16[3][3], B16[3];
    #pragma unroll
    for (int m = 0; m < 3; m++) {
        const int j = 3 * r + m;
        #pragma unroll
        for (int k = 0; k < 5; k++) WX16[m][k] = __float2half2_rn(wih[j*5+k]);
        #pragma unroll
        for (int i = 0; i < 3; i++) {
            WhO16[m][i] = __float2half2_rn(whh[j*9 + 3*r  + i]);
            WhA16[m][i] = __float2half2_rn(whh[j*9 + 3*rA + i]);
            WhB16[m][i] = __float2half2_rn(whh[j*9 + 3*rB + i]);
        }
        B16[m] = __float2half2_rn(bih[j] + bhh[j]);
    }

    // ---- cp.async loader (verbatim R8/R12/R13) ---------------------------
    const char* xc = (const char*)x;
    u64      gsrc[7];
    unsigned sdst[7];
    {
        unsigned sbase = (unsigned)__cvta_generic_to_shared(&sx4[wIn][0][0]);
        #pragma unroll
        for (int k = 0; k < 7; k++) {
            int id = lane + 32 * k;
            int idc = min(id, 199);
            int slot = idc / 10, c = idc - 10 * slot;
            int b = min(wg * TPW + slot, BB - 1);
            gsrc[k] = (u64)(xc + (size_t)b * (TT * 20) + (size_t)c * 16);
            sdst[k] = sbase + ((slot >> 1) * 21 + (slot & 1) * 10 + c) * 16;
        }
    }
    #define CPA(g, bufoff) do {                                               \
        u64 wb = (u64)(bwd ? (TT - 8 - 8 * (g)) : (8 * (g))) * 20;            \
        _Pragma("unroll")                                                     \
        for (int k = 0; k < 7; k++)                                           \
            if (lane + 32 * k < 200)                                          \
                asm volatile("cp.async.cg.shared.global [%0], [%1], 16;\n"    \
                    :: "r"(sdst[k] + (bufoff)), "l"(gsrc[k] + wb));           \
        asm volatile("cp.async.commit_group;\n");                             \
    } while (0)
    const unsigned BUFB = 210 * 16;

    __half2 h16[3], Ha16[3], Hb16[3];
    #pragma unroll
    for (int i = 0; i < 3; i++) {
        h16[i] = __float2half2_rn(0.f);
        Ha16[i] = __float2half2_rn(0.f);
        Hb16[i] = __float2half2_rn(0.f);
    }
    __half2 Xh[20];
    __half2 zx16[4][3];

    #define LOADX(buf, half) do {                                             \
        const float4* s4 = &sx4[wIn][buf][tri * 21 + (half) * 5];             \
        float4 a0 = s4[0],  a1 = s4[1],  a2 = s4[2],  a3 = s4[3],  a4 = s4[4];\
        float4 c0 = s4[10], c1 = s4[11], c2 = s4[12], c3 = s4[13], c4 = s4[14];\
        Xh[0]=__floats2half2_rn(a0.x,c0.x);  Xh[1]=__floats2half2_rn(a0.y,c0.y);\
        Xh[2]=__floats2half2_rn(a0.z,c0.z);  Xh[3]=__floats2half2_rn(a0.w,c0.w);\
        Xh[4]=__floats2half2_rn(a1.x,c1.x);  Xh[5]=__floats2half2_rn(a1.y,c1.y);\
        Xh[6]=__floats2half2_rn(a1.z,c1.z);  Xh[7]=__floats2half2_rn(a1.w,c1.w);\
        Xh[8]=__floats2half2_rn(a2.x,c2.x);  Xh[9]=__floats2half2_rn(a2.y,c2.y);\
        Xh[10]=__floats2half2_rn(a2.z,c2.z); Xh[11]=__floats2half2_rn(a2.w,c2.w);\
        Xh[12]=__floats2half2_rn(a3.x,c3.x); Xh[13]=__floats2half2_rn(a3.y,c3.y);\
        Xh[14]=__floats2half2_rn(a3.z,c3.z); Xh[15]=__floats2half2_rn(a3.w,c3.w);\
        Xh[16]=__floats2half2_rn(a4.x,c4.x); Xh[17]=__floats2half2_rn(a4.y,c4.y);\
        Xh[18]=__floats2half2_rn(a4.z,c4.z); Xh[19]=__floats2half2_rn(a4.w,c4.w);\
    } while (0)

    #define ZXM(q, m) do {                                                    \
        __half2 z = __hfma2(WX16[m][0], Xh[(q)*5+0], B16[m]);                 \
        z = __hfma2(WX16[m][1], Xh[(q)*5+1], z);                              \
        z = __hfma2(WX16[m][2], Xh[(q)*5+2], z);                              \
        z = __hfma2(WX16[m][3], Xh[(q)*5+3], z);                              \
        z = __hfma2(WX16[m][4], Xh[(q)*5+4], z);                              \
        zx16[q][m] = z;                                                       \
    } while (0)

    #define ZXQ(q) do { ZXM(q, 0); ZXM(q, 1); ZXM(q, 2); } while (0)

    // step with interleaved exchange: t-chains (old H) first, then per-m
    // tanh -> 2 shfl -> next-step zx chunk (adjacent independent work).
    #define STEP16(q, HASZ, qz) do {                                          \
        __half2 tt[3];                                                        \
        _Pragma("unroll")                                                     \
        for (int m = 0; m < 3; m++) {                                         \
            __half2 t = __hfma2(WhO16[m][0], h16[0], zx16[q][m]);             \
            t = __hfma2(WhO16[m][1], h16[1], t);                              \
            t = __hfma2(WhO16[m][2], h16[2], t);                              \
            t = __hfma2(WhA16[m][0], Ha16[0], t);                             \
            t = __hfma2(WhA16[m][1], Ha16[1], t);                             \
            t = __hfma2(WhA16[m][2], Ha16[2], t);                             \
            __half2 u = __hmul2(WhB16[m][0], Hb16[0]);                        \
            u = __hfma2(WhB16[m][1], Hb16[1], u);                             \
            u = __hfma2(WhB16[m][2], Hb16[2], u);                             \
            tt[m] = __hadd2(t, u);                                            \
        }                                                                     \
        __half2 n0 = tanh2(tt[0]);                                            \
        __half2 a0 = shfl_h2(n0, laneA);                                      \
        __half2 b0 = shfl_h2(n0, laneB);                                      \
        if (HASZ) ZXM(qz, 0);                                                 \
        __half2 n1 = tanh2(tt[1]);                                            \
        __half2 a1 = shfl_h2(n1, laneA);                                      \
        __half2 b1 = shfl_h2(n1, laneB);                                      \
        if (HASZ) ZXM(qz, 1);                                                 \
        __half2 n2 = tanh2(tt[2]);                                            \
        __half2 a2 = shfl_h2(n2, laneA);                                      \
        __half2 b2 = shfl_h2(n2, laneB);                                      \
        if (HASZ) ZXM(qz, 2);                                                 \
        h16[0] = n0; h16[1] = n1; h16[2] = n2;                                \
        Ha16[0] = a0; Ha16[1] = a1; Ha16[2] = a2;                             \
        Hb16[0] = b0; Hb16[1] = b1; Hb16[2] = b2;                             \
    } while (0)

    #define CONS16(buf) do {                                                  \
        if (!bwd) {                                                           \
            LOADX(buf, 0); ZXQ(0);                                            \
            STEP16(0, 1, 1); STEP16(1, 1, 2); STEP16(2, 1, 3); STEP16(3, 0, 0);\
            LOADX(buf, 1); ZXQ(0);                                            \
            STEP16(0, 1, 1); STEP16(1, 1, 2); STEP16(2, 1, 3); STEP16(3, 0, 0);\
        } else {                                                              \
            LOADX(buf, 1); ZXQ(3);                                            \
            STEP16(3, 1, 2); STEP16(2, 1, 1); STEP16(1, 1, 0); STEP16(0, 0, 0);\
            LOADX(buf, 0); ZXQ(3);                                            \
            STEP16(3, 1, 2); STEP16(2, 1, 1); STEP16(1, 1, 0); STEP16(0, 0, 0);\
        }                                                                     \
    } while (0)

    // ================= main f16 loop: windows 0 .. NWIN-5 =================
    CPA(0, 0);
    CPA(1, BUFB);
    for (int g = 0; g < NWIN - 4; g++) {
        asm volatile("cp.async.wait_group 1;\n");
        __syncwarp();
        CONS16(g & 1);
        __syncwarp();
        CPA(g + 2, (g & 1) ? BUFB : 0);
    }

    // ================= f32 tail: last 4 windows (32 steps) ================
    u64 WXF[3][5], WhOF[3][3], WhAF[3][3], WhBF[3][3], B2F[3];
    #pragma unroll
    for (int m = 0; m < 3; m++) {
        const int j = 3 * r + m;
        #pragma unroll
        for (int k = 0; k < 5; k++) { float w = wih[j*5+k]; WXF[m][k] = pack2(w, w); }
        #pragma unroll
        for (int i = 0; i < 3; i++) {
            float wo = whh[j*9 + 3*r  + i]; WhOF[m][i] = pack2(wo, wo);
            float wa = whh[j*9 + 3*rA + i]; WhAF[m][i] = pack2(wa, wa);
            float wb = whh[j*9 + 3*rB + i]; WhBF[m][i] = pack2(wb, wb);
        }
        float bv = bih[j] + bhh[j];
        B2F[m] = pack2(bv, bv);
    }
    u64 hP[3], Ha[3], Hb[3];
    #pragma unroll
    for (int m = 0; m < 3; m++) {
        float2 f0 = __half22float2(h16[m]);  hP[m] = pack2(f0.x, f0.y);
        float2 f1 = __half22float2(Ha16[m]); Ha[m] = pack2(f1.x, f1.y);
        float2 f2 = __half22float2(Hb16[m]); Hb[m] = pack2(f2.x, f2.y);
    }
    u64 zxw[4][3];

    #define ZXHF(buf, half) do {                                              \
        const float4* s4 = &sx4[wIn][buf][tri * 21 + (half) * 5];             \
        float4 a0 = s4[0],  a1 = s4[1],  a2 = s4[2],  a3 = s4[3],  a4 = s4[4];\
        float4 c0 = s4[10], c1 = s4[11], c2 = s4[12], c3 = s4[13], c4 = s4[14];\
        float fa[20], fb[20];                                                 \
        fa[0]=a0.x; fa[1]=a0.y; fa[2]=a0.z; fa[3]=a0.w;                       \
        fa[4]=a1.x; fa[5]=a1.y; fa[6]=a1.z; fa[7]=a1.w;                       \
        fa[8]=a2.x; fa[9]=a2.y; fa[10]=a2.z; fa[11]=a2.w;                     \
        fa[12]=a3.x; fa[13]=a3.y; fa[14]=a3.z; fa[15]=a3.w;                   \
        fa[16]=a4.x; fa[17]=a4.y; fa[18]=a4.z; fa[19]=a4.w;                   \
        fb[0]=c0.x; fb[1]=c0.y; fb[2]=c0.z; fb[3]=c0.w;                       \
        fb[4]=c1.x; fb[5]=c1.y; fb[6]=c1.z; fb[7]=c1.w;                       \
        fb[8]=c2.x; fb[9]=c2.y; fb[10]=c2.z; fb[11]=c2.w;                     \
        fb[12]=c3.x; fb[13]=c3.y; fb[14]=c3.z; fb[15]=c3.w;                   \
        fb[16]=c4.x; fb[17]=c4.y; fb[18]=c4.z; fb[19]=c4.w;                   \
        _Pragma("unroll")                                                     \
        for (int q = 0; q < 4; q++) {                                         \
            u64 X0 = pack2(fa[q*5+0], fb[q*5+0]);                             \
            u64 X1 = pack2(fa[q*5+1], fb[q*5+1]);                             \
            u64 X2 = pack2(fa[q*5+2], fb[q*5+2]);                             \
            u64 X3 = pack2(fa[q*5+3], fb[q*5+3]);                             \
            u64 X4 = pack2(fa[q*5+4], fb[q*5+4]);                             \
            _Pragma("unroll")                                                 \
            for (int m = 0; m < 3; m++) {                                     \
                u64 z = fma2(WXF[m][0], X0, B2F[m]);                          \
                z = fma2(WXF[m][1], X1, z); z = fma2(WXF[m][2], X2, z);       \
                z = fma2(WXF[m][3], X3, z); z = fma2(WXF[m][4], X4, z);       \
                zxw[q][m] = z;                                                \
            }                                                                 \
        }                                                                     \
    } while (0)

    #define STEPF(q) do {                                                     \
        u64 nh[3];                                                            \
        _Pragma("unroll")                                                     \
        for (int m = 0; m < 3; m++) {                                         \
            u64 t1 = fma2(WhOF[m][2], hP[2], zxw[q][m]);                      \
            t1 = fma2(WhOF[m][1], hP[1], t1);                                 \
            t1 = fma2(WhOF[m][0], hP[0], t1);                                 \
            u64 t2 = mul2(WhAF[m][0], Ha[0]);                                 \
            t2 = fma2(WhAF[m][1], Ha[1], t2); t2 = fma2(WhAF[m][2], Ha[2], t2);\
            u64 t3 = mul2(WhBF[m][0], Hb[0]);                                 \
            t3 = fma2(WhBF[m][1], Hb[1], t3); t3 = fma2(WhBF[m][2], Hb[2], t3);\
            u64 z = add2(add2(t1, t2), t3);                                   \
            float sa, sb; unpack2(z, sa, sb);                                 \
            nh[m] = pack2(ftanh(sa), ftanh(sb));                              \
        }                                                                     \
        hP[0] = nh[0]; hP[1] = nh[1]; hP[2] = nh[2];                          \
        Ha[0] = __shfl_sync(0xffffffffu, hP[0], laneA);                       \
        Ha[1] = __shfl_sync(0xffffffffu, hP[1], laneA);                       \
        Ha[2] = __shfl_sync(0xffffffffu, hP[2], laneA);                       \
        Hb[0] = __shfl_sync(0xffffffffu, hP[0], laneB);                       \
        Hb[1] = __shfl_sync(0xffffffffu, hP[1], laneB);                       \
        Hb[2] = __shfl_sync(0xffffffffu, hP[2], laneB);                       \
    } while (0)

    #define CONSF(buf) do {                                                   \
        if (!bwd) {                                                           \
            ZXHF(buf, 0); STEPF(0); STEPF(1); STEPF(2); STEPF(3);             \
            ZXHF(buf, 1); STEPF(0); STEPF(1); STEPF(2); STEPF(3);             \
        } else {                                                              \
            ZXHF(buf, 1); STEPF(3); STEPF(2); STEPF(1); STEPF(0);             \
            ZXHF(buf, 0); STEPF(3); STEPF(2); STEPF(1); STEPF(0);             \
        }                                                                     \
    } while (0)

    for (int g = NWIN - 4; g < NWIN; g++) {
        asm volatile("cp.async.wait_group 1;\n");
        __syncwarp();
        CONSF(g & 1);
        __syncwarp();
        if (g + 2 < NWIN) CPA(g + 2, (g & 1) ? BUFB : 0);
    }

    if (lane < 30) {
        const int dirOff = bwd ? 9 : 0;
        const int bA = wg * TPW + 2 * tri;
        const int bB = bA + 1;
        float a0, b0, a1, b1, a2, b2;
        unpack2(hP[0], a0, b0); unpack2(hP[1], a1, b1); unpack2(hP[2], a2, b2);
        if (bA < BB) {
            float* d = g_y + bA * 18 + dirOff + 3 * r;
            d[0] = a0; d[1] = a1; d[2] = a2;
        }
        if (bB < BB) {
            float* d = g_y + bB * 18 + dirOff + 3 * r;
            d[0] = b0; d[1] = b1; d[2] = b2;
        }
    }
    #undef CPA
    #undef LOADX
    #undef ZXM
    #undef ZXQ
    #undef STEP16
    #undef CONS16
    #undef ZXHF
    #undef STEPF
    #undef CONSF
}

// ---------------------------------------------------------------------------
// Stage 2: H2=32 RNN, 25 steps + linear 32->3. f32x2-packed recurrence
// (16 fma2 instead of 32 FFMA - exact f32 math), precise tanh.
// ---------------------------------------------------------------------------
__global__ __launch_bounds__(256) void rnn2_kernel(
    const float* __restrict__ wih2, const float* __restrict__ whh2,
    const float* __restrict__ bih2, const float* __restrict__ bhh2,
    const float* __restrict__ wout, const float* __restrict__ bout,
    float* __restrict__ out)
{
    __shared__ float swh[1024], swi[576], swo[96];
    __shared__ float hs[8][OUTLEN][32];

    const int tid = threadIdx.x;
    for (int i = tid; i < 1024; i += 256) swh[i] = whh2[i];
    for (int i = tid; i < 576;  i += 256) swi[i] = wih2[i];
    if (tid < 96) swo[tid] = wout[tid];
    __syncthreads();

    const int wIn = tid >> 5;
    const int j   = tid & 31;
    const int b   = blockIdx.x * 8 + wIn;

    // packed Wh: 16 u64, pairs (Wh[2c], Wh[2c+1])
    u64 Wp[16];
    {
        const float2* p = reinterpret_cast<const float2*>(&swh[j * 32]);
        #pragma unroll
        for (int c = 0; c < 16; c++) { float2 v = p[c]; Wp[c] = pack2(v.x, v.y); }
    }
    float Wi[18];
    {
        const float2* p = reinterpret_cast<const float2*>(&swi[j * 18]);
        #pragma unroll
        for (int c = 0; c < 9; c++) { float2 v = p[c]; Wi[2*c] = v.x; Wi[2*c+1] = v.y; }
    }
    const float bj = bih2[j] + bhh2[j];

    float z = bj;
    {
        const float2* yp = reinterpret_cast<const float2*>(g_y + (size_t)b * 18);
        #pragma unroll
        for (int c = 0; c < 9; c++) {
            float2 v = yp[c];
            z = fmaf(Wi[2*c], v.x, z);
            z = fmaf(Wi[2*c+1], v.y, z);
        }
    }
    float h = ftanh(z);
    hs[wIn][0][j] = h;

    for (int t = 1; t < OUTLEN; t++) {
        __syncwarp();
        const u64* hp = reinterpret_cast<const u64*>(&hs[wIn][t - 1][0]);
        u64 a0 = fma2(Wp[0], hp[0], pack2(bj, 0.f));
        u64 a1 = mul2(Wp[1], hp[1]);
        u64 a2 = mul2(Wp[2], hp[2]);
        u64 a3 = mul2(Wp[3], hp[3]);
        #pragma unroll
        for (int c = 4; c < 16; c += 4) {
            a0 = fma2(Wp[c + 0], hp[c + 0], a0);
            a1 = fma2(Wp[c + 1], hp[c + 1], a1);
            a2 = fma2(Wp[c + 2], hp[c + 2], a2);
            a3 = fma2(Wp[c + 3], hp[c + 3], a3);
        }
        u64 s = add2(add2(a0, a1), add2(a2, a3));
        float slo, shi; unpack2(s, slo, shi);
        h = ftanh(slo + shi);
        hs[wIn][t][j] = h;
    }
    __syncwarp();

    float* op = out + (size_t)b * (OUTLEN * 3);
    for (int p = j; p < OUTLEN * 3; p += 32) {
        const int t = p / 3, o = p - 3 * t;
        const float4* yr = reinterpret_cast<const float4*>(&hs[wIn][t][0]);
        const float4* wr = reinterpret_cast<const float4*>(&swo[o * 32]);
        float acc = bout[o];
        #pragma unroll
        for (int c = 0; c < 8; c++) {
            float4 yv = yr[c], wv = wr[c];
            acc = fmaf(yv.x, wv.x, acc);
            acc = fmaf(yv.y, wv.y, acc);
            acc = fmaf(yv.z, wv.z, acc);
            acc = fmaf(yv.w, wv.w, acc);
        }
        op[p] = acc;
    }
}

// ---------------------------------------------------------------------------
// Launch pattern [rnn1, rnn2, dummy] kept: ncu capture stays on rnn1.
// ---------------------------------------------------------------------------
extern "C" void kernel_launch(void* const* d_in, const int* in_sizes, int n_in,
                              void* d_out, int out_size)
{
    const float* x     = (const float*)d_in[0];
    const float* wih_f = (const float*)d_in[1];
    const float* whh_f = (const float*)d_in[2];
    const float* bih_f = (const float*)d_in[3];
    const float* bhh_f = (const float*)d_in[4];
    const float* wih_b = (const float*)d_in[5];
    const float* whh_b = (const float*)d_in[6];
    const float* bih_b = (const float*)d_in[7];
    const float* bhh_b = (const float*)d_in[8];
    const float* wih2  = (const float*)d_in[9];
    const float* whh2  = (const float*)d_in[10];
    const float* bih2  = (const float*)d_in[11];
    const float* bhh2  = (const float*)d_in[12];
    const float* wout  = (const float*)d_in[13];
    const float* bout  = (const float*)d_in[14];
    float* out = (float*)d_out;

    // 103 CTAs x 4 warps = 412 warps (410 active), 1 CTA/SM, 1 warp/SMSP
    rnn1_kernel<<<103, 128>>>(x, wih_f, whh_f, bih_f, bhh_f,
                              wih_b, whh_b, bih_b, bhh_b);
    rnn2_kernel<<<512, 256>>>(wih2, whh2, bih2, bhh2, wout, bout, out);
    dummy_kernel<<<1, 32>>>();
}

// round 17
// speedup vs baseline: 1.0795x; 1.0795x over previous
#include <cuda_runtime.h>
#include <cuda_fp16.h>
typedef unsigned long long u64;

#define TT 2048
#define BB 4096
#define OUTLEN 25
#define TPW 20             // batches per warp: 10 pairs x 2 packed
#define WPD 205            // warps per direction
#define NWIN (TT/8)        // 256 windows of 8 steps

__device__ float g_y[BB * 18];

__device__ __forceinline__ u64 pack2(float lo, float hi) {
    u64 d; asm("mov.b64 %0,{%1,%2};" : "=l"(d) : "f"(lo), "f"(hi)); return d;
}
__device__ __forceinline__ void unpack2(u64 v, float& lo, float& hi) {
    asm("mov.b64 {%0,%1},%2;" : "=f"(lo), "=f"(hi) : "l"(v));
}
__device__ __forceinline__ u64 fma2(u64 a, u64 b, u64 c) {
    u64 d; asm("fma.rn.f32x2 %0,%1,%2,%3;" : "=l"(d) : "l"(a), "l"(b), "l"(c)); return d;
}
__device__ __forceinline__ u64 mul2(u64 a, u64 b) {
    u64 d; asm("mul.rn.f32x2 %0,%1,%2;" : "=l"(d) : "l"(a), "l"(b)); return d;
}
__device__ __forceinline__ u64 add2(u64 a, u64 b) {
    u64 d; asm("add.rn.f32x2 %0,%1,%2;" : "=l"(d) : "l"(a), "l"(b)); return d;
}
__device__ __forceinline__ __half2 tanh2(__half2 z) {
    unsigned zi = *reinterpret_cast<unsigned*>(&z);
    unsigned y; asm("tanh.approx.f16x2 %0,%1;" : "=r"(y) : "r"(zi));
    return *reinterpret_cast<__half2*>(&y);
}
__device__ __forceinline__ __half2 shfl_h2(__half2 v, int src) {
    unsigned u = *reinterpret_cast<unsigned*>(&v);
    u = __shfl_sync(0xffffffffu, u, src);
    return *reinterpret_cast<__half2*>(&u);
}
__device__ __forceinline__ float ftanh(float x) {
    x = fminf(fmaxf(x, -9.0f), 9.0f);
    float e = __expf(2.0f * x);
    return __fdividef(e - 1.0f, e + 1.0f);
}

__global__ void dummy_kernel() {}

// ---------------------------------------------------------------------------
// Stage 1: bidirectional Elman RNN H1=9 over T=2048. EXACT R13 kernel
// (measured 179.1us; R16's shfl-interleave variant regressed to 186.7 and is
// reverted). 410 warps = 103 CTAs x 4, 1 warp/SMSP; cp.async f32 x staging;
// f16x2 main phase with 1-step-ahead zx; f32x2 precise tail (last 32 steps).
// ---------------------------------------------------------------------------
__global__ __launch_bounds__(128, 1) void rnn1_kernel(
    const float* __restrict__ x,
    const float* __restrict__ wih_f, const float* __restrict__ whh_f,
    const float* __restrict__ bih_f, const float* __restrict__ bhh_f,
    const float* __restrict__ wih_b, const float* __restrict__ whh_b,
    const float* __restrict__ bih_b, const float* __restrict__ bhh_b)
{
    __shared__ float4 sx4[4][2][210];

    const int wIn  = threadIdx.x >> 5;
    const int lane = threadIdx.x & 31;
    const int wid  = blockIdx.x * 4 + wIn;
    if (wid >= 2 * WPD) return;

    const bool bwd = (wid >= WPD);
    const int  wg  = bwd ? wid - WPD : wid;
    const int  tri = min(lane / 3, 9);
    const int  r   = lane % 3;
    const int  rA  = (r + 1) % 3, rB = (r + 2) % 3;
    const int  laneA = 3 * tri + rA, laneB = 3 * tri + rB;

    const float* wih = bwd ? wih_b : wih_f;
    const float* whh = bwd ? whh_b : whh_f;
    const float* bih = bwd ? bih_b : bih_f;
    const float* bhh = bwd ? bhh_b : bhh_f;

    __half2 WX16[3][5], WhO16[3][3], WhA16[3][3], WhB16[3][3], B16[3];
    #pragma unroll
    for (int m = 0; m < 3; m++) {
        const int j = 3 * r + m;
        #pragma unroll
        for (int k = 0; k < 5; k++) WX16[m][k] = __float2half2_rn(wih[j*5+k]);
        #pragma unroll
        for (int i = 0; i < 3; i++) {
            WhO16[m][i] = __float2half2_rn(whh[j*9 + 3*r  + i]);
            WhA16[m][i] = __float2half2_rn(whh[j*9 + 3*rA + i]);
            WhB16[m][i] = __float2half2_rn(whh[j*9 + 3*rB + i]);
        }
        B16[m] = __float2half2_rn(bih[j] + bhh[j]);
    }

    const char* xc = (const char*)x;
    u64      gsrc[7];
    unsigned sdst[7];
    {
        unsigned sbase = (unsigned)__cvta_generic_to_shared(&sx4[wIn][0][0]);
        #pragma unroll
        for (int k = 0; k < 7; k++) {
            int id = lane + 32 * k;
            int idc = min(id, 199);
            int slot = idc / 10, c = idc - 10 * slot;
            int b = min(wg * TPW + slot, BB - 1);
            gsrc[k] = (u64)(xc + (size_t)b * (TT * 20) + (size_t)c * 16);
            sdst[k] = sbase + ((slot >> 1) * 21 + (slot & 1) * 10 + c) * 16;
        }
    }
    #define CPA(g, bufoff) do {                                               \
        u64 wb = (u64)(bwd ? (TT - 8 - 8 * (g)) : (8 * (g))) * 20;            \
        _Pragma("unroll")                                                     \
        for (int k = 0; k < 7; k++)                                           \
            if (lane + 32 * k < 200)                                          \
                asm volatile("cp.async.cg.shared.global [%0], [%1], 16;\n"    \
                    :: "r"(sdst[k] + (bufoff)), "l"(gsrc[k] + wb));           \
        asm volatile("cp.async.commit_group;\n");                             \
    } while (0)
    const unsigned BUFB = 210 * 16;

    __half2 h16[3], Ha16[3], Hb16[3];
    #pragma unroll
    for (int i = 0; i < 3; i++) {
        h16[i] = __float2half2_rn(0.f);
        Ha16[i] = __float2half2_rn(0.f);
        Hb16[i] = __float2half2_rn(0.f);
    }
    __half2 Xh[20];
    __half2 zx16[4][3];

    #define LOADX(buf, half) do {                                             \
        const float4* s4 = &sx4[wIn][buf][tri * 21 + (half) * 5];             \
        float4 a0 = s4[0],  a1 = s4[1],  a2 = s4[2],  a3 = s4[3],  a4 = s4[4];\
        float4 c0 = s4[10], c1 = s4[11], c2 = s4[12], c3 = s4[13], c4 = s4[14];\
        Xh[0]=__floats2half2_rn(a0.x,c0.x);  Xh[1]=__floats2half2_rn(a0.y,c0.y);\
        Xh[2]=__floats2half2_rn(a0.z,c0.z);  Xh[3]=__floats2half2_rn(a0.w,c0.w);\
        Xh[4]=__floats2half2_rn(a1.x,c1.x);  Xh[5]=__floats2half2_rn(a1.y,c1.y);\
        Xh[6]=__floats2half2_rn(a1.z,c1.z);  Xh[7]=__floats2half2_rn(a1.w,c1.w);\
        Xh[8]=__floats2half2_rn(a2.x,c2.x);  Xh[9]=__floats2half2_rn(a2.y,c2.y);\
        Xh[10]=__floats2half2_rn(a2.z,c2.z); Xh[11]=__floats2half2_rn(a2.w,c2.w);\
        Xh[12]=__floats2half2_rn(a3.x,c3.x); Xh[13]=__floats2half2_rn(a3.y,c3.y);\
        Xh[14]=__floats2half2_rn(a3.z,c3.z); Xh[15]=__floats2half2_rn(a3.w,c3.w);\
        Xh[16]=__floats2half2_rn(a4.x,c4.x); Xh[17]=__floats2half2_rn(a4.y,c4.y);\
        Xh[18]=__floats2half2_rn(a4.z,c4.z); Xh[19]=__floats2half2_rn(a4.w,c4.w);\
    } while (0)

    #define ZXQ(q) do {                                                       \
        _Pragma("unroll")                                                     \
        for (int m = 0; m < 3; m++) {                                         \
            __half2 z = __hfma2(WX16[m][0], Xh[(q)*5+0], B16[m]);             \
            z = __hfma2(WX16[m][1], Xh[(q)*5+1], z);                          \
            z = __hfma2(WX16[m][2], Xh[(q)*5+2], z);                          \
            z = __hfma2(WX16[m][3], Xh[(q)*5+3], z);                          \
            z = __hfma2(WX16[m][4], Xh[(q)*5+4], z);                          \
            zx16[q][m] = z;                                                   \
        }                                                                     \
    } while (0)

    #define STEP16(q, HASZ, qz) do {                                          \
        if (HASZ) ZXQ(qz);                                                    \
        __half2 nh[3];                                                        \
        _Pragma("unroll")                                                     \
        for (int m = 0; m < 3; m++) {                                         \
            __half2 t = __hfma2(WhO16[m][0], h16[0], zx16[q][m]);             \
            t = __hfma2(WhO16[m][1], h16[1], t);                              \
            t = __hfma2(WhO16[m][2], h16[2], t);                              \
            t = __hfma2(WhA16[m][0], Ha16[0], t);                             \
            t = __hfma2(WhA16[m][1], Ha16[1], t);                             \
            t = __hfma2(WhA16[m][2], Ha16[2], t);                             \
            __half2 u = __hmul2(WhB16[m][0], Hb16[0]);                        \
            u = __hfma2(WhB16[m][1], Hb16[1], u);                             \
            u = __hfma2(WhB16[m][2], Hb16[2], u);                             \
            nh[m] = tanh2(__hadd2(t, u));                                     \
        }                                                                     \
        h16[0] = nh[0]; h16[1] = nh[1]; h16[2] = nh[2];                       \
        Ha16[0] = shfl_h2(h16[0], laneA);                                     \
        Ha16[1] = shfl_h2(h16[1], laneA);                                     \
        Ha16[2] = shfl_h2(h16[2], laneA);                                     \
        Hb16[0] = shfl_h2(h16[0], laneB);                                     \
        Hb16[1] = shfl_h2(h16[1], laneB);                                     \
        Hb16[2] = shfl_h2(h16[2], laneB);                                     \
    } while (0)

    #define CONS16(buf) do {                                                  \
        if (!bwd) {                                                           \
            LOADX(buf, 0); ZXQ(0);                                            \
            STEP16(0, 1, 1); STEP16(1, 1, 2); STEP16(2, 1, 3); STEP16(3, 0, 0);\
            LOADX(buf, 1); ZXQ(0);                                            \
            STEP16(0, 1, 1); STEP16(1, 1, 2); STEP16(2, 1, 3); STEP16(3, 0, 0);\
        } else {                                                              \
            LOADX(buf, 1); ZXQ(3);                                            \
            STEP16(3, 1, 2); STEP16(2, 1, 1); STEP16(1, 1, 0); STEP16(0, 0, 0);\
            LOADX(buf, 0); ZXQ(3);                                            \
            STEP16(3, 1, 2); STEP16(2, 1, 1); STEP16(1, 1, 0); STEP16(0, 0, 0);\
        }                                                                     \
    } while (0)

    CPA(0, 0);
    CPA(1, BUFB);
    for (int g = 0; g < NWIN - 4; g++) {
        asm volatile("cp.async.wait_group 1;\n");
        __syncwarp();
        CONS16(g & 1);
        __syncwarp();
        CPA(g + 2, (g & 1) ? BUFB : 0);
    }

    // f32 tail: last 4 windows (32 steps)
    u64 WXF[3][5], WhOF[3][3], WhAF[3][3], WhBF[3][3], B2F[3];
    #pragma unroll
    for (int m = 0; m < 3; m++) {
        const int j = 3 * r + m;
        #pragma unroll
        for (int k = 0; k < 5; k++) { float w = wih[j*5+k]; WXF[m][k] = pack2(w, w); }
        #pragma unroll
        for (int i = 0; i < 3; i++) {
            float wo = whh[j*9 + 3*r  + i]; WhOF[m][i] = pack2(wo, wo);
            float wa = whh[j*9 + 3*rA + i]; WhAF[m][i] = pack2(wa, wa);
            float wb = whh[j*9 + 3*rB + i]; WhBF[m][i] = pack2(wb, wb);
        }
        float bv = bih[j] + bhh[j];
        B2F[m] = pack2(bv, bv);
    }
    u64 hP[3], Ha[3], Hb[3];
    #pragma unroll
    for (int m = 0; m < 3; m++) {
        float2 f0 = __half22float2(h16[m]);  hP[m] = pack2(f0.x, f0.y);
        float2 f1 = __half22float2(Ha16[m]); Ha[m] = pack2(f1.x, f1.y);
        float2 f2 = __half22float2(Hb16[m]); Hb[m] = pack2(f2.x, f2.y);
    }
    u64 zxw[4][3];

    #define ZXHF(buf, half) do {                                              \
        const float4* s4 = &sx4[wIn][buf][tri * 21 + (half) * 5];             \
        float4 a0 = s4[0],  a1 = s4[1],  a2 = s4[2],  a3 = s4[3],  a4 = s4[4];\
        float4 c0 = s4[10], c1 = s4[11], c2 = s4[12], c3 = s4[13], c4 = s4[14];\
        float fa[20], fb[20];                                                 \
        fa[0]=a0.x; fa[1]=a0.y; fa[2]=a0.z; fa[3]=a0.w;                       \
        fa[4]=a1.x; fa[5]=a1.y; fa[6]=a1.z; fa[7]=a1.w;                       \
        fa[8]=a2.x; fa[9]=a2.y; fa[10]=a2.z; fa[11]=a2.w;                     \
        fa[12]=a3.x; fa[13]=a3.y; fa[14]=a3.z; fa[15]=a3.w;                   \
        fa[16]=a4.x; fa[17]=a4.y; fa[18]=a4.z; fa[19]=a4.w;                   \
        fb[0]=c0.x; fb[1]=c0.y; fb[2]=c0.z; fb[3]=c0.w;                       \
        fb[4]=c1.x; fb[5]=c1.y; fb[6]=c1.z; fb[7]=c1.w;                       \
        fb[8]=c2.x; fb[9]=c2.y; fb[10]=c2.z; fb[11]=c2.w;                     \
        fb[12]=c3.x; fb[13]=c3.y; fb[14]=c3.z; fb[15]=c3.w;                   \
        fb[16]=c4.x; fb[17]=c4.y; fb[18]=c4.z; fb[19]=c4.w;                   \
        _Pragma("unroll")                                                     \
        for (int q = 0; q < 4; q++) {                                         \
            u64 X0 = pack2(fa[q*5+0], fb[q*5+0]);                             \
            u64 X1 = pack2(fa[q*5+1], fb[q*5+1]);                             \
            u64 X2 = pack2(fa[q*5+2], fb[q*5+2]);                             \
            u64 X3 = pack2(fa[q*5+3], fb[q*5+3]);                             \
            u64 X4 = pack2(fa[q*5+4], fb[q*5+4]);                             \
            _Pragma("unroll")                                                 \
            for (int m = 0; m < 3; m++) {                                     \
                u64 z = fma2(WXF[m][0], X0, B2F[m]);                          \
                z = fma2(WXF[m][1], X1, z); z = fma2(WXF[m][2], X2, z);       \
                z = fma2(WXF[m][3], X3, z); z = fma2(WXF[m][4], X4, z);       \
                zxw[q][m] = z;                                                \
            }                                                                 \
        }                                                                     \
    } while (0)

    #define STEPF(q) do {                                                     \
        u64 nh[3];                                                            \
        _Pragma("unroll")                                                     \
        for (int m = 0; m < 3; m++) {                                         \
            u64 t1 = fma2(WhOF[m][2], hP[2], zxw[q][m]);                      \
            t1 = fma2(WhOF[m][1], hP[1], t1);                                 \
            t1 = fma2(WhOF[m][0], hP[0], t1);                                 \
            u64 t2 = mul2(WhAF[m][0], Ha[0]);                                 \
            t2 = fma2(WhAF[m][1], Ha[1], t2); t2 = fma2(WhAF[m][2], Ha[2], t2);\
            u64 t3 = mul2(WhBF[m][0], Hb[0]);                                 \
            t3 = fma2(WhBF[m][1], Hb[1], t3); t3 = fma2(WhBF[m][2], Hb[2], t3);\
            u64 z = add2(add2(t1, t2), t3);                                   \
            float sa, sb; unpack2(z, sa, sb);                                 \
            nh[m] = pack2(ftanh(sa), ftanh(sb));                              \
        }                                                                     \
        hP[0] = nh[0]; hP[1] = nh[1]; hP[2] = nh[2];                          \
        Ha[0] = __shfl_sync(0xffffffffu, hP[0], laneA);                       \
        Ha[1] = __shfl_sync(0xffffffffu, hP[1], laneA);                       \
        Ha[2] = __shfl_sync(0xffffffffu, hP[2], laneA);                       \
        Hb[0] = __shfl_sync(0xffffffffu, hP[0], laneB);                       \
        Hb[1] = __shfl_sync(0xffffffffu, hP[1], laneB);                       \
        Hb[2] = __shfl_sync(0xffffffffu, hP[2], laneB);                       \
    } while (0)

    #define CONSF(buf) do {                                                   \
        if (!bwd) {                                                           \
            ZXHF(buf, 0); STEPF(0); STEPF(1); STEPF(2); STEPF(3);             \
            ZXHF(buf, 1); STEPF(0); STEPF(1); STEPF(2); STEPF(3);             \
        } else {                                                              \
            ZXHF(buf, 1); STEPF(3); STEPF(2); STEPF(1); STEPF(0);             \
            ZXHF(buf, 0); STEPF(3); STEPF(2); STEPF(1); STEPF(0);             \
        }                                                                     \
    } while (0)

    for (int g = NWIN - 4; g < NWIN; g++) {
        asm volatile("cp.async.wait_group 1;\n");
        __syncwarp();
        CONSF(g & 1);
        __syncwarp();
        if (g + 2 < NWIN) CPA(g + 2, (g & 1) ? BUFB : 0);
    }

    if (lane < 30) {
        const int dirOff = bwd ? 9 : 0;
        const int bA = wg * TPW + 2 * tri;
        const int bB = bA + 1;
        float a0, b0, a1, b1, a2, b2;
        unpack2(hP[0], a0, b0); unpack2(hP[1], a1, b1); unpack2(hP[2], a2, b2);
        if (bA < BB) {
            float* d = g_y + bA * 18 + dirOff + 3 * r;
            d[0] = a0; d[1] = a1; d[2] = a2;
        }
        if (bB < BB) {
            float* d = g_y + bB * 18 + dirOff + 3 * r;
            d[0] = b0; d[1] = b1; d[2] = b2;
        }
    }
    #undef CPA
    #undef LOADX
    #undef ZXQ
    #undef STEP16
    #undef CONS16
    #undef ZXHF
    #undef STEPF
    #undef CONSF
}

// ---------------------------------------------------------------------------
// Stage 2: H2=32 RNN, 25 steps + linear 32->3. Same arithmetic as the 27us
// R4/R13 version, with the two 32-way smem bank conflicts fixed:
//  (1) Whh staged TRANSPOSED (wht[i*32+j]) -> per-lane register fill reads
//      lane-consecutive addresses (was stride-128B, 32-way conflict x8).
//  (2) hs rows padded 32 -> 36 floats -> epilogue per-lane row reads spread
//      across banks (was bank-aligned, ~32-way conflict x8).
// ---------------------------------------------------------------------------
__global__ __launch_bounds__(256) void rnn2_kernel(
    const float* __restrict__ wih2, const float* __restrict__ whh2,
    const float* __restrict__ bih2, const float* __restrict__ bhh2,
    const float* __restrict__ wout, const float* __restrict__ bout,
    float* __restrict__ out)
{
    __shared__ float wht[1024];           // transposed Whh: wht[i*32+j]
    __shared__ float swi[576], swo[96];
    __shared__ float hs[8][OUTLEN][36];   // padded rows (36 floats)

    const int tid = threadIdx.x;
    // transposed fill: dest d -> source (d%32)*32 + d/32; STS conflict-free
    for (int d = tid; d < 1024; d += 256) wht[d] = whh2[(d & 31) * 32 + (d >> 5)];
    for (int i = tid; i < 576;  i += 256) swi[i] = wih2[i];
    if (tid < 96) swo[tid] = wout[tid];
    __syncthreads();

    const int wIn = tid >> 5;
    const int j   = tid & 31;
    const int b   = blockIdx.x * 8 + wIn;

    // conflict-free register fill: lane j reads wht[i*32 + j] (consecutive)
    float Wh[32];
    #pragma unroll
    for (int i = 0; i < 32; i++) Wh[i] = wht[i * 32 + j];

    float Wi[18];
    {
        const float2* p = reinterpret_cast<const float2*>(&swi[j * 18]);
        #pragma unroll
        for (int c = 0; c < 9; c++) { float2 v = p[c]; Wi[2*c] = v.x; Wi[2*c+1] = v.y; }
    }
    const float bj = bih2[j] + bhh2[j];

    float z = bj;
    {
        const float2* yp = reinterpret_cast<const float2*>(g_y + (size_t)b * 18);
        #pragma unroll
        for (int c = 0; c < 9; c++) {
            float2 v = yp[c];
            z = fmaf(Wi[2*c], v.x, z);
            z = fmaf(Wi[2*c+1], v.y, z);
        }
    }
    float h = ftanh(z);
    hs[wIn][0][j] = h;

    for (int t = 1; t < OUTLEN; t++) {
        __syncwarp();
        const float4* hp = reinterpret_cast<const float4*>(&hs[wIn][t - 1][0]);
        float a0 = bj, a1 = 0.f, a2 = 0.f, a3 = 0.f;
        #pragma unroll
        for (int c = 0; c < 8; c += 4) {
            float4 v0 = hp[c],     v1 = hp[c + 1];
            float4 v2 = hp[c + 2], v3 = hp[c + 3];
            a0 = fmaf(Wh[4*c+0],  v0.x, a0); a0 = fmaf(Wh[4*c+1],  v0.y, a0);
            a1 = fmaf(Wh[4*c+2],  v0.z, a1); a1 = fmaf(Wh[4*c+3],  v0.w, a1);
            a2 = fmaf(Wh[4*c+4],  v1.x, a2); a2 = fmaf(Wh[4*c+5],  v1.y, a2);
            a3 = fmaf(Wh[4*c+6],  v1.z, a3); a3 = fmaf(Wh[4*c+7],  v1.w, a3);
            a0 = fmaf(Wh[4*c+8],  v2.x, a0); a0 = fmaf(Wh[4*c+9],  v2.y, a0);
            a1 = fmaf(Wh[4*c+10], v2.z, a1); a1 = fmaf(Wh[4*c+11], v2.w, a1);
            a2 = fmaf(Wh[4*c+12], v3.x, a2); a2 = fmaf(Wh[4*c+13], v3.y, a2);
            a3 = fmaf(Wh[4*c+14], v3.z, a3); a3 = fmaf(Wh[4*c+15], v3.w, a3);
        }
        h = ftanh((a0 + a1) + (a2 + a3));
        hs[wIn][t][j] = h;
    }
    __syncwarp();

    float* op = out + (size_t)b * (OUTLEN * 3);
    for (int p = j; p < OUTLEN * 3; p += 32) {
        const int t = p / 3, o = p - 3 * t;
        const float4* yr = reinterpret_cast<const float4*>(&hs[wIn][t][0]);
        const float4* wr = reinterpret_cast<const float4*>(&swo[o * 32]);
        float acc = bout[o];
        #pragma unroll
        for (int c = 0; c < 8; c++) {
            float4 yv = yr[c], wv = wr[c];
            acc = fmaf(yv.x, wv.x, acc);
            acc = fmaf(yv.y, wv.y, acc);
            acc = fmaf(yv.z, wv.z, acc);
            acc = fmaf(yv.w, wv.w, acc);
        }
        op[p] = acc;
    }
}

// ---------------------------------------------------------------------------
// Launch pattern [rnn1, rnn2, dummy] kept: ncu capture stays on rnn1.
// ---------------------------------------------------------------------------
extern "C" void kernel_launch(void* const* d_in, const int* in_sizes, int n_in,
                              void* d_out, int out_size)
{
    const float* x     = (const float*)d_in[0];
    const float* wih_f = (const float*)d_in[1];
    const float* whh_f = (const float*)d_in[2];
    const float* bih_f = (const float*)d_in[3];
    const float* bhh_f = (const float*)d_in[4];
    const float* wih_b = (const float*)d_in[5];
    const float* whh_b = (const float*)d_in[6];
    const float* bih_b = (const float*)d_in[7];
    const float* bhh_b = (const float*)d_in[8];
    const float* wih2  = (const float*)d_in[9];
    const float* whh2  = (const float*)d_in[10];
    const float* bih2  = (const float*)d_in[11];
    const float* bhh2  = (const float*)d_in[12];
    const float* wout  = (const float*)d_in[13];
    const float* bout  = (const float*)d_in[14];
    float* out = (float*)d_out;

    // 103 CTAs x 4 warps = 412 warps (410 active), 1 CTA/SM, 1 warp/SMSP
    rnn1_kernel<<<103, 128>>>(x, wih_f, whh_f, bih_f, bhh_f,
                              wih_b, whh_b, bih_b, bhh_b);
    rnn2_kernel<<<512, 256>>>(wih2, whh2, bih2, bhh2, wout, bout, out);
    dummy_kernel<<<1, 32>>>();
}